// round 14
// baseline (speedup 1.0000x reference)
#include <cuda_runtime.h>
#include <cuda_bf16.h>
#include <cstdint>

// Problem constants
#define T_DIM   64
#define NCH     2048
#define KDIM    65536
#define THRESHV 16384.0f
#define KWTA    16

// GEMM config: 16 n-blocks x SPLITK 18 = 288 CTAs (all resident at occ 2)
#define SPLITK  18
#define BK      16
#define NCTAS   288
#define POSTBLK 64

// fp32 staging ring: 4 stages x (A 4KB, B 8KB)
#define FPSTG   12288
#define FP_B    4096
// bf16 ring: 3 stages x 18432 (AH 0, AL 3072, BH 6144, BL 12288; 48B rows)
#define BFBASE  49152
#define BFSTG   18432
#define RSTRIDE 48
#define AH_OFF  0
#define AL_OFF  3072
#define BH_OFF  6144
#define BL_OFF  12288
#define SMEM_TOTAL (BFBASE + 3 * BFSTG)   // 104448

// Post-phase smem aliases (into the same dynamic buffer)
#define PS_POT   0        // float [64][32]   8192 B
#define PS_TOT   8192     // float [2048]     8192 B
#define PS_COEF  16384    // float [2048]     8192 B
#define PS_WV    24576    // float [32]
#define PS_WI    24704    // int   [32]
#define PS_BC    24832    // float
#define PS_TGT   24836    // uint

#define FXSCALE 1048576.0f               // 2^20 fixed-point scale
#define FXINV   (1.0 / 1048576.0)

// Static scratch (no allocations allowed).
// g_pot_fix is SELF-CLEANING: zero at module load; post phase re-zeroes it
// after reading, so every launch (and every graph replay) starts from zero.
__device__ unsigned long long g_pot_fix[T_DIM * NCH];   // 1 MB
__device__ int   g_cnt[NCH];
__device__ float g_fp[NCH];
__device__ unsigned int g_tickA = 0;   // monotonic: +288 per launch
__device__ unsigned int g_tickB = 0;   // monotonic: +64 per launch

// ---------------------------------------------------------------------------
// Helpers
// ---------------------------------------------------------------------------
__device__ __forceinline__ uint32_t smem_u32(const void* p) {
    uint32_t a;
    asm("{ .reg .u64 t; cvta.to.shared.u64 t, %1; cvt.u32.u64 %0, t; }"
        : "=r"(a) : "l"(p));
    return a;
}
__device__ __forceinline__ void cp16(uint32_t dst, const void* src) {
    asm volatile("cp.async.cg.shared.global [%0], [%1], 16;"
                 :: "r"(dst), "l"(src) : "memory");
}
#define CP_COMMIT() asm volatile("cp.async.commit_group;" ::: "memory")
#define CP_WAIT(n)  asm volatile("cp.async.wait_group %0;" :: "n"(n) : "memory")

// Split float2 -> hi bf16x2 (RN) + lo bf16x2 (residual). Proven exact R3-R13.
__device__ __forceinline__ void split2(float x, float y, uint32_t& h, uint32_t& l) {
    asm("cvt.rn.bf16x2.f32 %0, %1, %2;" : "=r"(h) : "f"(y), "f"(x));
    float hx = __uint_as_float(h << 16);
    float hy = __uint_as_float(h & 0xFFFF0000u);
    float lx = x - hx;
    float ly = y - hy;
    asm("cvt.rn.bf16x2.f32 %0, %1, %2;" : "=r"(l) : "f"(ly), "f"(lx));
}

__device__ __forceinline__ void mma16816(float* c, const uint32_t* a,
                                         uint32_t b0, uint32_t b1) {
    asm volatile(
        "mma.sync.aligned.m16n8k16.row.col.f32.bf16.bf16.f32 "
        "{%0,%1,%2,%3}, {%4,%5,%6,%7}, {%8,%9}, {%0,%1,%2,%3};"
        : "+f"(c[0]), "+f"(c[1]), "+f"(c[2]), "+f"(c[3])
        : "r"(a[0]), "r"(a[1]), "r"(a[2]), "r"(a[3]), "r"(b0), "r"(b1));
}

__device__ __forceinline__ void ldsm4(uint32_t* r, uint32_t addr) {
    asm volatile("ldmatrix.sync.aligned.m8n8.x4.shared.b16 {%0,%1,%2,%3}, [%4];"
                 : "=r"(r[0]), "=r"(r[1]), "=r"(r[2]), "=r"(r[3]) : "r"(addr));
}

__device__ __forceinline__ void cvt_sts(const char* fp, char* hiP, char* loP) {
    float4 v = *(const float4*)fp;
    uint32_t h0, l0, h1, l1;
    split2(v.x, v.y, h0, l0);
    split2(v.z, v.w, h1, l1);
    *(uint2*)hiP = make_uint2(h0, h1);
    *(uint2*)loP = make_uint2(l0, l1);
}

// (val, idx) comparator: higher val wins, tie -> lower idx. Matches lax.top_k.
__device__ __forceinline__ void cmb(float& bv, int& bi, float ov, int oi) {
    if (ov > bv || (ov == bv && oi < bi)) { bv = ov; bi = oi; }
}

// Deterministic fixed-point accumulate (integer add is order-independent).
__device__ __forceinline__ void atom_acc(unsigned long long* p, float v) {
    long long q = llrintf(v * FXSCALE);   // *2^20 exact; only llrintf rounds
    atomicAdd(p, (unsigned long long)q);
}

// ---------------------------------------------------------------------------
// Single fused kernel: GEMM mainloop + atomic epilogue + grid sync + post.
// ---------------------------------------------------------------------------
__global__ void __launch_bounds__(256, 2)
gemm_fused(const float* __restrict__ rec, const float* __restrict__ w,
           float* __restrict__ out) {
    extern __shared__ char sm[];
    const uint32_t sbase = smem_u32(sm);

    const int tid  = threadIdx.x;
    const int wid  = tid >> 5;
    const int lane = tid & 31;
    const int g    = lane >> 2;
    const int q    = lane & 3;
    const int wm   = wid >> 2;
    const int wn   = wid & 3;
    const int nblk = blockIdx.x * 128;
    const int s    = blockIdx.y;
    const int flat = blockIdx.y * 16 + blockIdx.x;
    const int nit  = (s < 10) ? 228 : 227;
    const int ch0  = (s < 10) ? s * 228 : 2280 + (s - 10) * 227;
    const size_t k0 = (size_t)ch0 * BK;

    const int lr  = tid >> 2;
    const int lkc = (tid & 3) * 4;
    const float* aS  = rec + (size_t)lr * KDIM + k0 + lkc;
    const float* bS0 = w + (size_t)(nblk + lr) * KDIM + k0 + lkc;
    const float* bS1 = bS0 + (size_t)64 * KDIM;
    const uint32_t fpA = (uint32_t)lr * 64 + lkc * 4;
    const uint32_t fpB = FP_B + (uint32_t)lr * 64 + lkc * 4;
    const uint32_t bfO = (uint32_t)lr * RSTRIDE + lkc * 2;

    const int j  = lane >> 3;
    const int l7 = lane & 7;
    const uint32_t aOff = (uint32_t)(wm * 32 + (j & 1) * 8 + l7) * RSTRIDE
                        + (j >> 1) * 16 + AH_OFF;
    const uint32_t bOff = (uint32_t)(wn * 32 + (j >> 1) * 8 + l7) * RSTRIDE
                        + (j & 1) * 16 + BH_OFF;

    float acc[2][4][4];
    #pragma unroll
    for (int m = 0; m < 2; m++)
        #pragma unroll
        for (int n = 0; n < 4; n++)
            #pragma unroll
            for (int i = 0; i < 4; i++) acc[m][n][i] = 0.0f;

    #pragma unroll
    for (int st = 0; st < 3; st++) {
        const uint32_t fo = sbase + st * FPSTG;
        const int co = st * BK;
        cp16(fo + fpA, aS + co);
        cp16(fo + fpB, bS0 + co);
        cp16(fo + fpB + 4096, bS1 + co);
        CP_COMMIT();
    }
    CP_WAIT(2);
    {
        const char* fs = sm;
        char* bs = sm + BFBASE;
        cvt_sts(fs + fpA, bs + AH_OFF + bfO, bs + AL_OFF + bfO);
        cvt_sts(fs + fpB, bs + BH_OFF + bfO, bs + BL_OFF + bfO);
        cvt_sts(fs + fpB + 4096, bs + BH_OFF + 3072 + bfO, bs + BL_OFF + 3072 + bfO);
    }

    int bfc = 0;

    #pragma unroll 1
    for (int it = 0; it < nit; it++) {
        const int nc = it + 3;
        if (nc < nit) {
            const uint32_t fo = sbase + (nc & 3) * FPSTG;
            const int co = nc * BK;
            cp16(fo + fpA, aS + co);
            cp16(fo + fpB, bS0 + co);
            cp16(fo + fpB + 4096, bS1 + co);
        }
        CP_COMMIT();
        CP_WAIT(2);
        __syncthreads();

        const int bfn = (bfc == 2) ? 0 : bfc + 1;
        if (it + 1 < nit) {
            const char* fs = sm + ((it + 1) & 3) * FPSTG;
            char* bs = sm + BFBASE + bfn * BFSTG;
            cvt_sts(fs + fpA, bs + AH_OFF + bfO, bs + AL_OFF + bfO);
            cvt_sts(fs + fpB, bs + BH_OFF + bfO, bs + BL_OFF + bfO);
            cvt_sts(fs + fpB + 4096, bs + BH_OFF + 3072 + bfO,
                    bs + BL_OFF + 3072 + bfO);
        }

        const uint32_t sb = sbase + BFBASE + bfc * BFSTG;
        uint32_t Ah0[4], Ah1[4], Al0[4], Al1[4];
        ldsm4(Ah0, sb + aOff);
        ldsm4(Ah1, sb + aOff + 16 * RSTRIDE);
        ldsm4(Al0, sb + aOff + (AL_OFF - AH_OFF));
        ldsm4(Al1, sb + aOff + (AL_OFF - AH_OFF) + 16 * RSTRIDE);
        uint32_t Bh0[4], Bh1[4], Bl0[4], Bl1[4];
        ldsm4(Bh0, sb + bOff);
        ldsm4(Bh1, sb + bOff + 16 * RSTRIDE);
        ldsm4(Bl0, sb + bOff + (BL_OFF - BH_OFF));
        ldsm4(Bl1, sb + bOff + (BL_OFF - BH_OFF) + 16 * RSTRIDE);

        const uint32_t* Bh[4] = { &Bh0[0], &Bh0[2], &Bh1[0], &Bh1[2] };
        const uint32_t* Bl[4] = { &Bl0[0], &Bl0[2], &Bl1[0], &Bl1[2] };
        const uint32_t* Ah[2] = { Ah0, Ah1 };
        const uint32_t* Al[2] = { Al0, Al1 };

        #pragma unroll
        for (int m = 0; m < 2; m++) {
            #pragma unroll
            for (int n = 0; n < 4; n++) {
                mma16816(acc[m][n], Ah[m], Bh[n][0], Bh[n][1]);
                mma16816(acc[m][n], Ah[m], Bl[n][0], Bl[n][1]);
                mma16816(acc[m][n], Al[m], Bh[n][0], Bh[n][1]);
            }
        }
        bfc = bfn;
    }

    // Epilogue: deterministic fixed-point atomic accumulate
    const int t0 = wm * 32;
    #pragma unroll
    for (int m = 0; m < 2; m++) {
        const int r0 = t0 + m * 16 + g;
        #pragma unroll
        for (int n = 0; n < 4; n++) {
            const int cb = nblk + wn * 32 + n * 8 + 2 * q;
            unsigned long long* p0 = &g_pot_fix[r0 * NCH + cb];
            unsigned long long* p1 = &g_pot_fix[(r0 + 8) * NCH + cb];
            atom_acc(p0,     acc[m][n][0]);
            atom_acc(p0 + 1, acc[m][n][1]);
            atom_acc(p1,     acc[m][n][2]);
            atom_acc(p1 + 1, acc[m][n][3]);
        }
    }

    // ---- Grid sync A: all 288 CTAs arrive; only post blocks (flat<64) spin ----
    __threadfence();
    __syncthreads();
    volatile uint32_t* tgtp = (volatile uint32_t*)(sm + PS_TGT);
    if (tid == 0) {
        unsigned int tk = atomicAdd(&g_tickA, 1u);
        *tgtp = (tk / (unsigned)NCTAS + 1u) * (unsigned)NCTAS;
    }
    if (flat >= POSTBLK) return;          // non-post blocks: arrive and exit
    __syncthreads();
    if (tid == 0) {
        const unsigned int tgt = *tgtp;
        volatile unsigned int* vc = &g_tickA;
        while (*vc < tgt) { }
    }
    __syncthreads();
    __threadfence();

    // =========================== POST PHASE (64 blocks) ======================
    float* pot_s  = (float*)(sm + PS_POT);    // [64][32]
    float* tot_s  = (float*)(sm + PS_TOT);    // [2048]
    float* coef_s = (float*)(sm + PS_COEF);   // [2048]
    float* wv     = (float*)(sm + PS_WV);
    int*   wi     = (int*)(sm + PS_WI);
    float* bc_v   = (float*)(sm + PS_BC);

    const int colbase = flat * 32;

    // Phase 1: read fixed-point accumulators, convert, self-clean to zero.
    #pragma unroll
    for (int i = 0; i < 4; i++) {
        const int item = tid + i * 256;       // 0..1023
        const int t  = item >> 4;
        const int cp = item & 15;
        unsigned long long* gp = &g_pot_fix[t * NCH + colbase + cp * 2];
        const ulonglong2 v = *(const ulonglong2*)gp;
        *(ulonglong2*)gp = make_ulonglong2(0ull, 0ull);   // clean for next launch
        pot_s[t * 32 + cp * 2]     = (float)((double)(long long)v.x * FXINV);
        pot_s[t * 32 + cp * 2 + 1] = (float)((double)(long long)v.y * FXINV);
    }
    __syncthreads();

    // Per-column stats (32 threads scan 64 t's each; conflict-free LDS)
    if (tid < 32) {
        const int c = tid;
        int cnt = 0;
        #pragma unroll
        for (int t = 0; t < T_DIM; t++)
            if (pot_s[t * 32 + c] > THRESHV) cnt++;
        int fi = T_DIM - cnt;
        if (fi > T_DIM - 1) fi = T_DIM - 1;
        if (fi < 0) fi = 0;
        float o = pot_s[fi * 32 + c];
        g_cnt[colbase + c] = cnt;
        g_fp[colbase + c]  = (o > THRESHV) ? o : 0.0f;
    }

    // ---- Grid sync B among the 64 post blocks ----
    __threadfence();
    __syncthreads();
    if (tid == 0) {
        unsigned int tk = atomicAdd(&g_tickB, 1u);
        *tgtp = (tk / (unsigned)POSTBLK + 1u) * (unsigned)POSTBLK;
    }
    __syncthreads();
    if (tid == 0) {
        const unsigned int tgt = *tgtp;
        volatile unsigned int* vc = &g_tickB;
        while (*vc < tgt) { }
    }
    __syncthreads();
    __threadfence();

    // Phase 2: winners (redundant per block; 256 threads x 8 entries, = R9)
    int   cnts[8];
    float fps[8];
    float m = 0.0f;
    #pragma unroll
    for (int h = 0; h < 8; h++) {
        const int k = tid + h * 256;
        cnts[h] = g_cnt[k];
        fps[h]  = g_fp[k];
        m = fmaxf(m, (cnts[h] > 0) ? fps[h] : 0.0f);
    }
    #pragma unroll
    for (int o = 16; o > 0; o >>= 1)
        m = fmaxf(m, __shfl_down_sync(0xFFFFFFFFu, m, o));
    if (lane == 0) wv[wid] = m;
    __syncthreads();
    if (wid == 0) {
        float mm = (lane < 8) ? wv[lane] : 0.0f;
        #pragma unroll
        for (int o = 4; o > 0; o >>= 1)
            mm = fmaxf(mm, __shfl_down_sync(0xFFu, mm, o));
        if (lane == 0) *bc_v = mm * (float)T_DIM;
    }
    __syncthreads();
    const float v = *bc_v;

    #pragma unroll
    for (int h = 0; h < 8; h++) {
        const int k = tid + h * 256;
        const float term = fps[h] + v;
        float sacc = 0.0f;
        for (int i = 0; i < cnts[h]; i++) sacc += term;
        tot_s[k] = sacc;
        coef_s[k] = 0.0f;
    }
    __syncthreads();

    for (int it = 0; it < KWTA; it++) {
        float bv = -3.4e38f;
        int   bi = NCH;
        #pragma unroll
        for (int h = 0; h < 8; h++) {
            const int k = tid + h * 256;
            cmb(bv, bi, tot_s[k], k);
        }
        #pragma unroll
        for (int o = 16; o > 0; o >>= 1) {
            float ov = __shfl_down_sync(0xFFFFFFFFu, bv, o);
            int   oi = __shfl_down_sync(0xFFFFFFFFu, bi, o);
            cmb(bv, bi, ov, oi);
        }
        if (lane == 0) { wv[wid] = bv; wi[wid] = bi; }
        __syncthreads();
        if (wid == 0) {
            float fv = (lane < 8) ? wv[lane] : -3.4e38f;
            int   fi = (lane < 8) ? wi[lane] : NCH;
            #pragma unroll
            for (int o = 4; o > 0; o >>= 1) {
                float ov = __shfl_down_sync(0xFFu, fv, o);
                int   oi = __shfl_down_sync(0xFFu, fi, o);
                cmb(fv, fi, ov, oi);
            }
            if (lane == 0) {
                if (fv > 0.0f) coef_s[fi] = 1.0f;
                tot_s[fi] = -3.4e38f;
            }
        }
        __syncthreads();
    }

    // Phase 3: output from smem pot tile
    #pragma unroll
    for (int i = 0; i < 4; i++) {
        const int item = tid + i * 256;
        const int t  = item >> 4;
        const int cp = item & 15;
        const int col0 = colbase + cp * 2;
        const float cf0 = coef_s[col0];
        const float cf1 = coef_s[col0 + 1];
        float2 o2;
        o2.x = (pot_s[t * 32 + cp * 2]     > THRESHV && cf0 > 0.0f) ? 1.0f : 0.0f;
        o2.y = (pot_s[t * 32 + cp * 2 + 1] > THRESHV && cf1 > 0.0f) ? 1.0f : 0.0f;
        *(float2*)&out[t * NCH + col0] = o2;
    }
}

// ---------------------------------------------------------------------------
extern "C" void kernel_launch(void* const* d_in, const int* in_sizes, int n_in,
                              void* d_out, int out_size) {
    const float* rec = (const float*)d_in[0];   // (64, 1, 256, 256)
    const float* w   = (const float*)d_in[1];   // (2048, 1, 256, 256)
    float* out = (float*)d_out;                 // (64, 2048, 1, 1) float32

    cudaFuncSetAttribute(gemm_fused, cudaFuncAttributeMaxDynamicSharedMemorySize,
                         SMEM_TOTAL);
    dim3 grid(NCH / 128, SPLITK);               // (16, 18) = 288 CTAs, all resident
    gemm_fused<<<grid, 256, SMEM_TOTAL>>>(rec, w, out);
}